// round 3
// baseline (speedup 1.0000x reference)
#include <cuda_runtime.h>

typedef unsigned long long u64;

// Problem dims
#define B_ 2
#define N_ 512
#define T_ 12
#define E_ 128
#define H_ 8
#define D_ 16
#define BHT 192                // B*H*T
#define SLICE 8192             // N*D
#define HEADSZ (BHT*SLICE)
#define MROWS (B_*N_*T_)       // 12288

// Scratch: heads layout [B,H,T,N,D]
// 0:Qf 1:Kf 2:Vf 3:Qs 4:Ks 5:Vs 6:Qfs
__device__ float g_heads[7][HEADSZ];
__device__ float g_ctx[4][HEADSZ];
// Packed weights: [0..5]=proj W, [6]=Wout. Entry (k*64+c) = (W[k,c], W[k,c+64])
__device__ u64 g_Wp[7][8192];

// ---- packed fp32x2 helpers ----
__device__ __forceinline__ u64 pack2(float lo, float hi) {
    u64 r; asm("mov.b64 %0,{%1,%2};" : "=l"(r) : "f"(lo), "f"(hi)); return r;
}
__device__ __forceinline__ void unpack2(u64 v, float& lo, float& hi) {
    asm("mov.b64 {%0,%1},%2;" : "=f"(lo), "=f"(hi) : "l"(v));
}
__device__ __forceinline__ u64 fma2(u64 a, u64 b, u64 c) {
    u64 d; asm("fma.rn.f32x2 %0,%1,%2,%3;" : "=l"(d) : "l"(a), "l"(b), "l"(c)); return d;
}
__device__ __forceinline__ u64 mul2(u64 a, u64 b) {
    u64 d; asm("mul.rn.f32x2 %0,%1,%2;" : "=l"(d) : "l"(a), "l"(b)); return d;
}
__device__ __forceinline__ u64 add2(u64 a, u64 b) {
    u64 d; asm("add.rn.f32x2 %0,%1,%2;" : "=l"(d) : "l"(a), "l"(b)); return d;
}

struct ProjArgs {
    const float* x[6];
    const float* w[6];
    const float* kj;
    const float* vfp;
};
struct PackArgs { const float* w[7]; };

// ---------------------------------------------------------------------------
// Kernel 0: pack 7 weight matrices into u64 (c, c+64) pairs once.
// ---------------------------------------------------------------------------
__global__ __launch_bounds__(512) void pack_kernel(PackArgs pk) {
    const int p = blockIdx.x;
    const float* W = pk.w[p];
    for (int q = threadIdx.x; q < 8192; q += 512) {
        int k = q >> 6, c = q & 63;
        g_Wp[p][q] = pack2(W[k * 128 + c], W[k * 128 + c + 64]);
    }
}

// ---------------------------------------------------------------------------
// Kernel 1: input projections. X tile in smem; packed W via LDG (L1-hot).
// ---------------------------------------------------------------------------
__global__ __launch_bounds__(256) void proj_kernel(ProjArgs args) {
    extern __shared__ float sm[];
    float* Xs = sm;                  // 64*128 floats = 32KB
    const int p = blockIdx.y;
    const int tile = blockIdx.x;
    const int tid = threadIdx.x;

    const float* X = args.x[p] + (size_t)tile * 64 * 128;
    for (int i = tid; i < 2048; i += 256)
        ((float4*)Xs)[i] = ((const float4*)X)[i];
    __syncthreads();

    const u64* __restrict__ Wp = g_Wp[p];
    const int cg = tid & 15;
    const int rg = tid >> 4;
    const int r0 = rg << 2;

    u64 acc[4][4];
#pragma unroll
    for (int i = 0; i < 4; i++)
#pragma unroll
        for (int j = 0; j < 4; j++) acc[i][j] = 0ull;

    for (int k0 = 0; k0 < 128; k0 += 4) {
        float4 xv[4];
#pragma unroll
        for (int i = 0; i < 4; i++)
            xv[i] = *(const float4*)&Xs[(r0 + i) * 128 + k0];
#pragma unroll
        for (int kk = 0; kk < 4; kk++) {
            u64 w4[4];
#pragma unroll
            for (int j = 0; j < 4; j++)
                w4[j] = __ldg(&Wp[(k0 + kk) * 64 + cg + 16 * j]);
#pragma unroll
            for (int i = 0; i < 4; i++) {
                float xc = (kk == 0) ? xv[i].x : (kk == 1) ? xv[i].y : (kk == 2) ? xv[i].z : xv[i].w;
                u64 xa = pack2(xc, xc);
#pragma unroll
                for (int j = 0; j < 4; j++)
                    acc[i][j] = fma2(xa, w4[j], acc[i][j]);
            }
        }
    }

    const bool isQs = (p == 3);
#pragma unroll
    for (int i = 0; i < 4; i++) {
        int row = tile * 64 + r0 + i;
        int t = row % T_;
        int n = (row / T_) % N_;
        int b = row / (T_ * N_);
        float kj = 0.f, vfpi = 1.f;
        if (isQs) { kj = args.kj[n]; vfpi = args.vfp[n] + 1e-5f; }
#pragma unroll
        for (int j = 0; j < 4; j++) {
            float vlo, vhi; unpack2(acc[i][j], vlo, vhi);
            int h0 = j, h1 = j + 4;
            int idx0 = (((b * H_ + h0) * T_ + t) * N_ + n) * D_ + cg;
            int idx1 = (((b * H_ + h1) * T_ + t) * N_ + n) * D_ + cg;
            g_heads[p][idx0] = vlo;
            g_heads[p][idx1] = vhi;
            if (isQs) {
                g_heads[6][idx0] = kj * (vlo - vlo * vlo / vfpi);
                g_heads[6][idx1] = kj * (vhi - vhi * vhi / vfpi);
            }
        }
    }
}

// ---------------------------------------------------------------------------
// Kernel 2: attention. One block per (slice, att). 512 threads = 16 warps.
// Warp owns 4 query rows per pass; scores staged scaled-to-log2 in smem;
// exp2 fused into PV pass; f32x2 FMA throughout.
// ---------------------------------------------------------------------------
#define SCALE_LOG2 0.36067376022224085f   // (1/sqrt(16)) * log2(e)

__global__ __launch_bounds__(512) void attn_kernel() {
    extern __shared__ float sm[];
    float* Bs = sm;                  // 512*20
    float* Vs = sm + 10240;          // 512*20
    float* Sc = sm + 20480;          // 64*528

    const int slice = blockIdx.x;    // 0..191
    const int att = blockIdx.y;      // 0..3

    int ai, bi, vi;
    switch (att) {
        case 0:  ai = 0; bi = 1; vi = 2; break;  // ff: Qf,Kf,Vf
        case 1:  ai = 1; bi = 6; vi = 2; break;  // fs: Kf,Qfs,Vf
        case 2:  ai = 4; bi = 0; vi = 5; break;  // sf: Ks,Qf,Vs
        default: ai = 3; bi = 4; vi = 5; break;  // ss: Qs,Ks,Vs
    }

    const float* Ag = g_heads[ai] + slice * SLICE;
    const float* Bg = g_heads[bi] + slice * SLICE;
    const float* Vg = g_heads[vi] + slice * SLICE;
    float* Og = g_ctx[att] + slice * SLICE;

    const int tid = threadIdx.x;
    for (int i = tid; i < 2048; i += 512) {
        int r = i >> 2, s4 = i & 3;
        ((float4*)&Bs[r * 20])[s4] = ((const float4*)Bg)[i];
        ((float4*)&Vs[r * 20])[s4] = ((const float4*)Vg)[i];
    }
    __syncthreads();

    const int w = tid >> 5;
    const int lane = tid & 31;
    float* ScW = Sc + (w * 4) * 528;

    for (int pass = 0; pass < 8; pass++) {
        const int n0 = pass * 64 + w * 4;

        // ---- P1: scores (log2-scaled) + row max ----
        u64 a[4][8];
#pragma unroll
        for (int r = 0; r < 4; r++) {
            const u64* Ar = (const u64*)(Ag + (n0 + r) * 16);
#pragma unroll
            for (int j = 0; j < 8; j++) a[r][j] = Ar[j];
        }
        float mx[4] = {-3.0e38f, -3.0e38f, -3.0e38f, -3.0e38f};
#pragma unroll 4
        for (int k = 0; k < 16; k++) {
            int m = lane + 32 * k;
            const ulonglong2* Br = (const ulonglong2*)&Bs[m * 20];
            ulonglong2 b01 = Br[0], b23 = Br[1], b45 = Br[2], b67 = Br[3];
            u64 bb[8] = {b01.x, b01.y, b23.x, b23.y, b45.x, b45.y, b67.x, b67.y};
#pragma unroll
            for (int r = 0; r < 4; r++) {
                u64 s2 = mul2(a[r][0], bb[0]);
#pragma unroll
                for (int j = 1; j < 8; j++) s2 = fma2(a[r][j], bb[j], s2);
                float lo, hi; unpack2(s2, lo, hi);
                float s = (lo + hi) * SCALE_LOG2;
                ScW[r * 528 + m] = s;
                mx[r] = fmaxf(mx[r], s);
            }
        }
#pragma unroll
        for (int r = 0; r < 4; r++) {
            mx[r] = fmaxf(mx[r], __shfl_xor_sync(0xffffffffu, mx[r], 16));
            mx[r] = fmaxf(mx[r], __shfl_xor_sync(0xffffffffu, mx[r], 8));
            mx[r] = fmaxf(mx[r], __shfl_xor_sync(0xffffffffu, mx[r], 4));
            mx[r] = fmaxf(mx[r], __shfl_xor_sync(0xffffffffu, mx[r], 2));
            mx[r] = fmaxf(mx[r], __shfl_xor_sync(0xffffffffu, mx[r], 1));
        }

        // ---- P2: exp2 fused + PV accumulate + sum ----
        u64 acc[4][8];
#pragma unroll
        for (int r = 0; r < 4; r++)
#pragma unroll
            for (int j = 0; j < 8; j++) acc[r][j] = 0ull;
        float sum[4] = {0.f, 0.f, 0.f, 0.f};
#pragma unroll 4
        for (int k = 0; k < 16; k++) {
            int m = lane + 32 * k;
            float pe[4];
#pragma unroll
            for (int r = 0; r < 4; r++) {
                pe[r] = exp2f(ScW[r * 528 + m] - mx[r]);
                sum[r] += pe[r];
            }
            const ulonglong2* Vr = (const ulonglong2*)&Vs[m * 20];
            ulonglong2 v01 = Vr[0], v23 = Vr[1], v45 = Vr[2], v67 = Vr[3];
            u64 vv[8] = {v01.x, v01.y, v23.x, v23.y, v45.x, v45.y, v67.x, v67.y};
#pragma unroll
            for (int r = 0; r < 4; r++) {
                u64 pp = pack2(pe[r], pe[r]);
#pragma unroll
                for (int j = 0; j < 8; j++)
                    acc[r][j] = fma2(pp, vv[j], acc[r][j]);
            }
        }
#pragma unroll
        for (int r = 0; r < 4; r++) {
            sum[r] += __shfl_xor_sync(0xffffffffu, sum[r], 16);
            sum[r] += __shfl_xor_sync(0xffffffffu, sum[r], 8);
            sum[r] += __shfl_xor_sync(0xffffffffu, sum[r], 4);
            sum[r] += __shfl_xor_sync(0xffffffffu, sum[r], 2);
            sum[r] += __shfl_xor_sync(0xffffffffu, sum[r], 1);
        }

        // ---- cross-lane acc reduction via conflict-free smem scratch ----
        u64* scr = (u64*)ScW;        // 4*528 floats = 1056 u64 = 32*33
        __syncwarp();
#pragma unroll
        for (int v = 0; v < 32; v++)
            scr[lane * 33 + v] = acc[v >> 3][v & 7];
        __syncwarp();
        u64 tot = scr[lane];
#pragma unroll 8
        for (int l2 = 1; l2 < 32; l2++)
            tot = add2(tot, scr[l2 * 33 + lane]);

        int r = lane >> 3, j = lane & 7;
        float inv = 1.0f / sum[r];
        float lo, hi; unpack2(tot, lo, hi);
        *(float2*)&Og[(n0 + r) * 16 + j * 2] = make_float2(lo * inv, hi * inv);
        __syncwarp();
    }
}

// ---------------------------------------------------------------------------
// Kernel 3: output projection. Gather ctx tile -> smem; packed Wout via LDG.
// ---------------------------------------------------------------------------
__global__ __launch_bounds__(256) void outproj_kernel(
    const float* __restrict__ bout, float* __restrict__ out) {
    extern __shared__ float sm[];
    float* Xs = sm;                  // 64*128 floats
    const int att = blockIdx.y;
    const int tile = blockIdx.x;
    const int tid = threadIdx.x;

    const float* ctx = g_ctx[att];
    for (int i = tid; i < 2048; i += 256) {
        int rr = i >> 5;
        int f4 = i & 31;
        int row = tile * 64 + rr;
        int t = row % T_;
        int n = (row / T_) % N_;
        int b = row / (T_ * N_);
        int h = f4 >> 2;
        int ds = (f4 & 3) << 2;
        int idx = (((b * H_ + h) * T_ + t) * N_ + n) * D_ + ds;
        *(float4*)&Xs[rr * 128 + (f4 << 2)] = *(const float4*)&ctx[idx];
    }
    __syncthreads();

    const u64* __restrict__ Wp = g_Wp[6];
    const int cg = tid & 15;
    const int rg = tid >> 4;
    const int r0 = rg << 2;

    u64 acc[4][4];
#pragma unroll
    for (int i = 0; i < 4; i++)
#pragma unroll
        for (int j = 0; j < 4; j++) acc[i][j] = 0ull;

    for (int k0 = 0; k0 < 128; k0 += 4) {
        float4 xv[4];
#pragma unroll
        for (int i = 0; i < 4; i++)
            xv[i] = *(const float4*)&Xs[(r0 + i) * 128 + k0];
#pragma unroll
        for (int kk = 0; kk < 4; kk++) {
            u64 w4[4];
#pragma unroll
            for (int j = 0; j < 4; j++)
                w4[j] = __ldg(&Wp[(k0 + kk) * 64 + cg + 16 * j]);
#pragma unroll
            for (int i = 0; i < 4; i++) {
                float xc = (kk == 0) ? xv[i].x : (kk == 1) ? xv[i].y : (kk == 2) ? xv[i].z : xv[i].w;
                u64 xa = pack2(xc, xc);
#pragma unroll
                for (int j = 0; j < 4; j++)
                    acc[i][j] = fma2(xa, w4[j], acc[i][j]);
            }
        }
    }

    float blo[4], bhi[4];
#pragma unroll
    for (int j = 0; j < 4; j++) {
        blo[j] = __ldg(&bout[cg + 16 * j]);
        bhi[j] = __ldg(&bout[cg + 16 * j + 64]);
    }

    float* outp = out + (size_t)att * MROWS * E_;
#pragma unroll
    for (int i = 0; i < 4; i++) {
        int row = tile * 64 + r0 + i;
#pragma unroll
        for (int j = 0; j < 4; j++) {
            float vlo, vhi; unpack2(acc[i][j], vlo, vhi);
            outp[row * 128 + cg + 16 * j]      = vlo + blo[j];
            outp[row * 128 + cg + 16 * j + 64] = vhi + bhi[j];
        }
    }
}

// ---------------------------------------------------------------------------
extern "C" void kernel_launch(void* const* d_in, const int* in_sizes, int n_in,
                              void* d_out, int out_size) {
    ProjArgs pa;
    PackArgs pk;
    for (int i = 0; i < 6; i++) {
        pa.x[i] = (const float*)d_in[i];
        pa.w[i] = (const float*)d_in[6 + i];
        pk.w[i] = (const float*)d_in[6 + i];
    }
    pa.kj  = (const float*)d_in[12];
    pa.vfp = (const float*)d_in[13];
    pk.w[6] = (const float*)d_in[14];
    const float* bout = (const float*)d_in[15];
    float* out = (float*)d_out;

    const int smemProj = 64 * 128 * 4;              // 32KB
    const int smemAttn = (20480 + 64 * 528) * 4;    // 217088 B

    cudaFuncSetAttribute(proj_kernel, cudaFuncAttributeMaxDynamicSharedMemorySize, smemProj);
    cudaFuncSetAttribute(attn_kernel, cudaFuncAttributeMaxDynamicSharedMemorySize, smemAttn);
    cudaFuncSetAttribute(outproj_kernel, cudaFuncAttributeMaxDynamicSharedMemorySize, smemProj);

    pack_kernel<<<7, 512>>>(pk);
    proj_kernel<<<dim3(192, 6), 256, smemProj>>>(pa);
    attn_kernel<<<dim3(192, 4), 512, smemAttn>>>();
    outproj_kernel<<<dim3(192, 4), 256, smemProj>>>(bout, out);
}